// round 12
// baseline (speedup 1.0000x reference)
#include <cuda_runtime.h>
#include <cuda_bf16.h>

// Problem constants
#define BB 2
#define TT 4096
#define EE 768
#define HH 12
#define SS 64
#define WW 256
#define CC 16
#define NN (BB * TT)   // 8192

// ---------------------------------------------------------------------------
// Packed split-bf16 scratch (device globals: allocation-free)
// Each uint32 = bf16(hi) in low 16 bits | bf16(residual) in high 16 bits.
// ---------------------------------------------------------------------------
__device__ unsigned g_xp[(size_t)NN * EE];
__device__ unsigned g_wp[(size_t)3 * EE * EE];
__device__ unsigned g_qp[(size_t)BB * HH * TT * SS];   // [b][h][t][d]
__device__ unsigned g_kp[(size_t)BB * HH * TT * SS];
__device__ unsigned g_vp[(size_t)BB * HH * TT * SS];

// ---------------------------------------------------------------------------
// Helpers
// ---------------------------------------------------------------------------
__device__ __forceinline__ unsigned pack2bf(float lo_elem, float hi_elem) {
    unsigned r;
    asm("cvt.rn.bf16x2.f32 %0, %1, %2;" : "=r"(r) : "f"(hi_elem), "f"(lo_elem));
    return r;
}
__device__ __forceinline__ unsigned pack_split(float v) {
    float hf = __bfloat162float(__float2bfloat16(v));
    return pack2bf(v, v - hf);   // low = hi-part, high = residual
}
__device__ __forceinline__ unsigned smaddr(const void* p) {
    return (unsigned)__cvta_generic_to_shared(p);
}
__device__ __forceinline__ void ldm_x4(unsigned a, unsigned& r0, unsigned& r1,
                                       unsigned& r2, unsigned& r3) {
    asm volatile("ldmatrix.sync.aligned.m8n8.x4.shared.b16 {%0,%1,%2,%3},[%4];"
                 : "=r"(r0), "=r"(r1), "=r"(r2), "=r"(r3) : "r"(a));
}
__device__ __forceinline__ void ldm_x4t(unsigned a, unsigned& r0, unsigned& r1,
                                        unsigned& r2, unsigned& r3) {
    asm volatile("ldmatrix.sync.aligned.m8n8.x4.trans.shared.b16 {%0,%1,%2,%3},[%4];"
                 : "=r"(r0), "=r"(r1), "=r"(r2), "=r"(r3) : "r"(a));
}
__device__ __forceinline__ void mma_bf16(float* d, const unsigned* a,
                                         unsigned b0, unsigned b1) {
    asm volatile(
        "mma.sync.aligned.m16n8k16.row.col.f32.bf16.bf16.f32 "
        "{%0,%1,%2,%3},{%4,%5,%6,%7},{%8,%9},{%0,%1,%2,%3};"
        : "+f"(d[0]), "+f"(d[1]), "+f"(d[2]), "+f"(d[3])
        : "r"(a[0]), "r"(a[1]), "r"(a[2]), "r"(a[3]), "r"(b0), "r"(b1));
}
// Truncated split of fp32: hi = upper 16 bits as bf16 (exact truncation),
// residual = v - hi (exact in fp32).
__device__ __forceinline__ float trunc_resid(float v) {
    unsigned bits = __float_as_uint(v) & 0xFFFF0000u;
    return v - __uint_as_float(bits);
}

// ---------------------------------------------------------------------------
// Pass 0: fp32 -> packed split-bf16 for x and the three weights, one launch.
// ---------------------------------------------------------------------------
#define NX4 (NN * EE / 4)
#define NW4 (EE * EE / 4)
#define NTOT4 (NX4 + 3 * NW4)

__global__ __launch_bounds__(256) void convert_kernel(
    const float* __restrict__ x,  const float* __restrict__ wq,
    const float* __restrict__ wk, const float* __restrict__ wv)
{
    int i = blockIdx.x * 256 + threadIdx.x;
    if (i >= NTOT4) return;
    const float4* src;
    unsigned* dstbase;
    int j;
    if (i < NX4)                  { src = (const float4*)x;  dstbase = g_xp;              j = i; }
    else if (i < NX4 + NW4)       { src = (const float4*)wq; dstbase = g_wp;              j = i - NX4; }
    else if (i < NX4 + 2 * NW4)   { src = (const float4*)wk; dstbase = g_wp + EE * EE;     j = i - NX4 - NW4; }
    else                          { src = (const float4*)wv; dstbase = g_wp + 2 * EE * EE; j = i - NX4 - 2 * NW4; }
    float4 v = src[j];
    uint4 o;
    o.x = pack_split(v.x); o.y = pack_split(v.y);
    o.z = pack_split(v.z); o.w = pack_split(v.w);
    ((uint4*)dstbase)[j] = o;
}

// ---------------------------------------------------------------------------
// Pass 1: Q/K/V = x @ W^T via mma.sync bf16, split accumulation (3 mma).
// 128x128 tile, k-step 16, 256 threads = 8 warps (2x4), warp tile 64x32.
// (unchanged from the 473us champion)
// ---------------------------------------------------------------------------
#define QST 24

__global__ __launch_bounds__(256) void qkv_mma_kernel()
{
    __shared__ __nv_bfloat16 Ah[128 * QST], Al[128 * QST];
    __shared__ __nv_bfloat16 Bh[128 * QST], Bl[128 * QST];

    const int which = blockIdx.z;
    const unsigned* wp = g_wp + (size_t)which * EE * EE;
    unsigned* dst = (which == 0) ? g_qp : (which == 1) ? g_kp : g_vp;
    const float scale = (which == 0) ? 0.125f : 1.0f;

    const int rowBase = blockIdx.x * 128;
    const int colBase = blockIdx.y * 128;
    const int t    = threadIdx.x;
    const int lane = t & 31;
    const int w    = t >> 5;
    const int wm   = (w >> 2) * 64;
    const int wn   = (w & 3) * 32;

    float acc[4][4][4];
    #pragma unroll
    for (int mt = 0; mt < 4; mt++)
        #pragma unroll
        for (int nt = 0; nt < 4; nt++)
            #pragma unroll
            for (int e = 0; e < 4; e++) acc[mt][nt][e] = 0.0f;

    uint4 pa[2], pb[2];
    #pragma unroll
    for (int j = 0; j < 2; j++) {
        const int s   = t + j * 256;
        const int row = s >> 2;
        const int q4  = (s & 3) * 4;
        pa[j] = *(const uint4*)&g_xp[(size_t)(rowBase + row) * EE + q4];
        pb[j] = *(const uint4*)&wp  [(size_t)(colBase + row) * EE + q4];
    }

    for (int k0 = 0; k0 < EE; k0 += 16) {
        __syncthreads();
        #pragma unroll
        for (int j = 0; j < 2; j++) {
            const int s   = t + j * 256;
            const int row = s >> 2;
            const int q4  = (s & 3) * 4;
            *(unsigned*)&Ah[row * QST + q4]     = __byte_perm(pa[j].x, pa[j].y, 0x5410);
            *(unsigned*)&Ah[row * QST + q4 + 2] = __byte_perm(pa[j].z, pa[j].w, 0x5410);
            *(unsigned*)&Al[row * QST + q4]     = __byte_perm(pa[j].x, pa[j].y, 0x7632);
            *(unsigned*)&Al[row * QST + q4 + 2] = __byte_perm(pa[j].z, pa[j].w, 0x7632);
            *(unsigned*)&Bh[row * QST + q4]     = __byte_perm(pb[j].x, pb[j].y, 0x5410);
            *(unsigned*)&Bh[row * QST + q4 + 2] = __byte_perm(pb[j].z, pb[j].w, 0x5410);
            *(unsigned*)&Bl[row * QST + q4]     = __byte_perm(pb[j].x, pb[j].y, 0x7632);
            *(unsigned*)&Bl[row * QST + q4 + 2] = __byte_perm(pb[j].z, pb[j].w, 0x7632);
        }
        __syncthreads();

        if (k0 + 16 < EE) {
            #pragma unroll
            for (int j = 0; j < 2; j++) {
                const int s   = t + j * 256;
                const int row = s >> 2;
                const int q4  = (s & 3) * 4;
                pa[j] = *(const uint4*)&g_xp[(size_t)(rowBase + row) * EE + k0 + 16 + q4];
                pb[j] = *(const uint4*)&wp  [(size_t)(colBase + row) * EE + k0 + 16 + q4];
            }
        }

        unsigned ah[4][4], al[4][4], bh[2][4], bl[2][4];
        #pragma unroll
        for (int mt = 0; mt < 4; mt++) {
            const int off = (wm + mt * 16 + (lane & 15)) * QST + ((lane >> 4) << 3);
            ldm_x4(smaddr(&Ah[off]), ah[mt][0], ah[mt][1], ah[mt][2], ah[mt][3]);
            ldm_x4(smaddr(&Al[off]), al[mt][0], al[mt][1], al[mt][2], al[mt][3]);
        }
        #pragma unroll
        for (int g = 0; g < 2; g++) {
            const int off = (wn + g * 16 + ((lane >> 4) << 3) + (lane & 7)) * QST
                          + (((lane >> 3) & 1) << 3);
            ldm_x4(smaddr(&Bh[off]), bh[g][0], bh[g][1], bh[g][2], bh[g][3]);
            ldm_x4(smaddr(&Bl[off]), bl[g][0], bl[g][1], bl[g][2], bl[g][3]);
        }
        #pragma unroll
        for (int mt = 0; mt < 4; mt++)
            #pragma unroll
            for (int nt = 0; nt < 4; nt++) {
                const int g  = nt >> 1;
                const int hb = (nt & 1) * 2;
                mma_bf16(acc[mt][nt], ah[mt], bh[g][hb], bh[g][hb + 1]);
                mma_bf16(acc[mt][nt], al[mt], bh[g][hb], bh[g][hb + 1]);
                mma_bf16(acc[mt][nt], ah[mt], bl[g][hb], bl[g][hb + 1]);
            }
    }

    #pragma unroll
    for (int mt = 0; mt < 4; mt++) {
        const int rg0 = rowBase + wm + mt * 16 + (lane >> 2);
        #pragma unroll
        for (int nt = 0; nt < 4; nt++) {
            const int jc = colBase + wn + nt * 8 + (lane & 3) * 2;
            const int h  = jc >> 6;
            const int d  = jc & 63;
            #pragma unroll
            for (int rh = 0; rh < 2; rh++) {
                const int rg = rg0 + rh * 8;
                const int bb = rg >> 12;
                const int tt = rg & (TT - 1);
                uint2 pv;
                pv.x = pack_split(acc[mt][nt][rh * 2 + 0] * scale);
                pv.y = pack_split(acc[mt][nt][rh * 2 + 1] * scale);
                *(uint2*)&dst[(((size_t)(bb * HH + h) * TT) + tt) * SS + d] = pv;
            }
        }
    }
}

// ---------------------------------------------------------------------------
// Pass 2: fused flash attention. Block = 256 q (full chunk) x (b,h); 8 warps,
// each warp owns TWO 16-row groups processed sequentially per staged K/V tile
// (halves staging work + K/V L2 traffic per query). Boundary chunks analytic.
// ---------------------------------------------------------------------------
#define KST 72
#define ATT_SMEM_ELEMS (4 * 128 * KST)
#define ATT_SMEM_BYTES (ATT_SMEM_ELEMS * 2)

__global__ __launch_bounds__(256) void attn_mma_kernel(float* __restrict__ out)
{
    extern __shared__ __nv_bfloat16 sm[];
    __nv_bfloat16* Kh = sm;
    __nv_bfloat16* Kl = sm + 128 * KST;
    __nv_bfloat16* Vh = sm + 2 * 128 * KST;
    __nv_bfloat16* Vl = sm + 3 * 128 * KST;

    const int c  = blockIdx.x;
    const int bh = blockIdx.y;
    const int b = bh / HH;
    const int h = bh % HH;

    const int t    = threadIdx.x;
    const int lane = t & 31;
    const int w    = t >> 5;

    // ---- stage Q (two 128-row groups through Kh/Kl), build Q frags ----
    unsigned qh[2][4][4], ql[2][4][4];
    #pragma unroll
    for (int grp = 0; grp < 2; grp++) {
        const unsigned* qb = g_qp + ((size_t)bh * TT + c * WW + grp * 128) * SS;
        if (grp) __syncthreads();       // group-0 frag reads done before overwrite
        #pragma unroll
        for (int i = 0; i < 8; i++) {
            const int s   = t + i * 256;
            const int row = s >> 4;
            const int q4  = (s & 15) * 4;
            uint4 v = *(const uint4*)&qb[row * SS + q4];
            *(uint2*)&Kh[row * KST + q4] =
                make_uint2(__byte_perm(v.x, v.y, 0x5410), __byte_perm(v.z, v.w, 0x5410));
            *(uint2*)&Kl[row * KST + q4] =
                make_uint2(__byte_perm(v.x, v.y, 0x7632), __byte_perm(v.z, v.w, 0x7632));
        }
        __syncthreads();
        #pragma unroll
        for (int kt = 0; kt < 4; kt++) {
            const int off = (w * 16 + (lane & 15)) * KST + kt * 16 + ((lane >> 4) << 3);
            ldm_x4(smaddr(&Kh[off]), qh[grp][kt][0], qh[grp][kt][1], qh[grp][kt][2], qh[grp][kt][3]);
            ldm_x4(smaddr(&Kl[off]), ql[grp][kt][0], ql[grp][kt][1], ql[grp][kt][2], ql[grp][kt][3]);
        }
    }

    float m[2][2], l[2][2];
    float o_fr[2][8][4];
    #pragma unroll
    for (int grp = 0; grp < 2; grp++) {
        m[grp][0] = m[grp][1] = -1e30f;
        l[grp][0] = l[grp][1] = 0.0f;
        #pragma unroll
        for (int nd = 0; nd < 8; nd++)
            #pragma unroll
            for (int e = 0; e < 4; e++) o_fr[grp][nd][e] = 0.0f;
    }

    const int rr = w * 16 + (lane >> 2);   // frag row-0 offset within 128-group

    // ---- analytic boundary-chunk contribution ----
    // zero-padded neighbor tiles contribute (row) / (255-row) unmasked
    // zero-scores to the softmax denominator, with V = 0.
    #pragma unroll
    for (int grp = 0; grp < 2; grp++) {
        const int rA = grp * 128 + rr;     // row within chunk, frag half 0
        const int rB = rA + 8;
        if (c == 0) {
            if (rA > 0) { m[grp][0] = 0.0f; l[grp][0] = (float)rA; }
            if (rB > 0) { m[grp][1] = 0.0f; l[grp][1] = (float)rB; }
        } else if (c == CC - 1) {
            const int aA = 255 - rA, aB = 255 - rB;
            if (aA > 0) { m[grp][0] = 0.0f; l[grp][0] = (float)aA; }
            if (aB > 0) { m[grp][1] = 0.0f; l[grp][1] = (float)aB; }
        }
    }

    const int tstart = (c == 0) ? 2 : 0;
    const int tend   = (c == CC - 1) ? 4 : 6;

    for (int nt = tstart; nt < tend; nt++) {
        const int kc = c - 1 + (nt >> 1);
        const int y0 = (nt & 1) * 128;
        const unsigned* kb = g_kp + ((size_t)bh * TT + kc * WW + y0) * SS;
        const unsigned* vb = g_vp + ((size_t)bh * TT + kc * WW + y0) * SS;

        __syncthreads();   // prior-tile smem reads done
        #pragma unroll
        for (int i = 0; i < 8; i++) {
            const int s   = t + i * 256;
            const int row = s >> 4;
            const int q4  = (s & 15) * 4;
            uint4 kv = *(const uint4*)&kb[row * SS + q4];
            uint4 vv = *(const uint4*)&vb[row * SS + q4];
            *(uint2*)&Kh[row * KST + q4] =
                make_uint2(__byte_perm(kv.x, kv.y, 0x5410), __byte_perm(kv.z, kv.w, 0x5410));
            *(uint2*)&Kl[row * KST + q4] =
                make_uint2(__byte_perm(kv.x, kv.y, 0x7632), __byte_perm(kv.z, kv.w, 0x7632));
            *(uint2*)&Vh[row * KST + q4] =
                make_uint2(__byte_perm(vv.x, vv.y, 0x5410), __byte_perm(vv.z, vv.w, 0x5410));
            *(uint2*)&Vl[row * KST + q4] =
                make_uint2(__byte_perm(vv.x, vv.y, 0x7632), __byte_perm(vv.z, vv.w, 0x7632));
        }
        __syncthreads();

        #pragma unroll
        for (int grp = 0; grp < 2; grp++) {
            // ---- QK ----
            float s_fr[16][4];
            #pragma unroll
            for (int n = 0; n < 16; n++)
                #pragma unroll
                for (int e = 0; e < 4; e++) s_fr[n][e] = 0.0f;

            #pragma unroll
            for (int kt = 0; kt < 4; kt++) {
                #pragma unroll
                for (int g = 0; g < 8; g++) {
                    unsigned kbf[4], klf[4];
                    const int off = (g * 16 + ((lane >> 4) << 3) + (lane & 7)) * KST
                                  + kt * 16 + (((lane >> 3) & 1) << 3);
                    ldm_x4(smaddr(&Kh[off]), kbf[0], kbf[1], kbf[2], kbf[3]);
                    ldm_x4(smaddr(&Kl[off]), klf[0], klf[1], klf[2], klf[3]);
                    #pragma unroll
                    for (int h2 = 0; h2 < 2; h2++) {
                        const int n = g * 2 + h2;
                        mma_bf16(s_fr[n], qh[grp][kt], kbf[h2 * 2], kbf[h2 * 2 + 1]);
                        mma_bf16(s_fr[n], ql[grp][kt], kbf[h2 * 2], kbf[h2 * 2 + 1]);
                        mma_bf16(s_fr[n], qh[grp][kt], klf[h2 * 2], klf[h2 * 2 + 1]);
                    }
                }
            }

            // ---- online softmax on fragments ----
            float rm0 = -1e30f, rm1 = -1e30f;
            #pragma unroll
            for (int n = 0; n < 16; n++) {
                rm0 = fmaxf(rm0, fmaxf(s_fr[n][0], s_fr[n][1]));
                rm1 = fmaxf(rm1, fmaxf(s_fr[n][2], s_fr[n][3]));
            }
            #pragma unroll
            for (int off = 1; off <= 2; off <<= 1) {
                rm0 = fmaxf(rm0, __shfl_xor_sync(0xFFFFFFFFu, rm0, off));
                rm1 = fmaxf(rm1, __shfl_xor_sync(0xFFFFFFFFu, rm1, off));
            }
            const float mn0 = fmaxf(m[grp][0], rm0);
            const float mn1 = fmaxf(m[grp][1], rm1);
            const float al0 = __expf(m[grp][0] - mn0);
            const float al1 = __expf(m[grp][1] - mn1);
            float rs0 = 0.0f, rs1 = 0.0f;
            #pragma unroll
            for (int n = 0; n < 16; n++) {
                s_fr[n][0] = __expf(s_fr[n][0] - mn0);
                s_fr[n][1] = __expf(s_fr[n][1] - mn0);
                s_fr[n][2] = __expf(s_fr[n][2] - mn1);
                s_fr[n][3] = __expf(s_fr[n][3] - mn1);
                rs0 += s_fr[n][0] + s_fr[n][1];
                rs1 += s_fr[n][2] + s_fr[n][3];
            }
            #pragma unroll
            for (int off = 1; off <= 2; off <<= 1) {
                rs0 += __shfl_xor_sync(0xFFFFFFFFu, rs0, off);
                rs1 += __shfl_xor_sync(0xFFFFFFFFu, rs1, off);
            }
            l[grp][0] = l[grp][0] * al0 + rs0;  m[grp][0] = mn0;
            l[grp][1] = l[grp][1] * al1 + rs1;  m[grp][1] = mn1;
            #pragma unroll
            for (int nd = 0; nd < 8; nd++) {
                o_fr[grp][nd][0] *= al0; o_fr[grp][nd][1] *= al0;
                o_fr[grp][nd][2] *= al1; o_fr[grp][nd][3] *= al1;
            }

            // ---- O += P @ V (truncated split of P; 3 mma) ----
            #pragma unroll
            for (int ktj = 0; ktj < 8; ktj++) {
                const float* pe = s_fr[2 * ktj];
                const float* po = s_fr[2 * ktj + 1];
                unsigned pah[4], pal[4];
                // hi parts: exact truncation to bf16 via PRMT on bit patterns
                pah[0] = __byte_perm(__float_as_uint(pe[0]), __float_as_uint(pe[1]), 0x7632);
                pah[1] = __byte_perm(__float_as_uint(pe[2]), __float_as_uint(pe[3]), 0x7632);
                pah[2] = __byte_perm(__float_as_uint(po[0]), __float_as_uint(po[1]), 0x7632);
                pah[3] = __byte_perm(__float_as_uint(po[2]), __float_as_uint(po[3]), 0x7632);
                // residuals (exact), rounded into bf16 pairs
                pal[0] = pack2bf(trunc_resid(pe[0]), trunc_resid(pe[1]));
                pal[1] = pack2bf(trunc_resid(pe[2]), trunc_resid(pe[3]));
                pal[2] = pack2bf(trunc_resid(po[0]), trunc_resid(po[1]));
                pal[3] = pack2bf(trunc_resid(po[2]), trunc_resid(po[3]));

                #pragma unroll
                for (int g = 0; g < 4; g++) {
                    unsigned vbf[4], vlf[4];
                    const int off = (ktj * 16 + (lane & 15)) * KST
                                  + g * 16 + ((lane >> 4) << 3);
                    ldm_x4t(smaddr(&Vh[off]), vbf[0], vbf[1], vbf[2], vbf[3]);
                    ldm_x4t(smaddr(&Vl[off]), vlf[0], vlf[1], vlf[2], vlf[3]);
                    #pragma unroll
                    for (int h2 = 0; h2 < 2; h2++) {
                        const int nd = g * 2 + h2;
                        mma_bf16(o_fr[grp][nd], pah, vbf[h2 * 2], vbf[h2 * 2 + 1]);
                        mma_bf16(o_fr[grp][nd], pal, vbf[h2 * 2], vbf[h2 * 2 + 1]);
                        mma_bf16(o_fr[grp][nd], pah, vlf[h2 * 2], vlf[h2 * 2 + 1]);
                    }
                }
            }
        }
    }

    // ---- epilogue: normalize + store fp32 ----
    #pragma unroll
    for (int grp = 0; grp < 2; grp++) {
        const float inv0 = 1.0f / l[grp][0];
        const float inv1 = 1.0f / l[grp][1];
        const int tr0 = c * WW + grp * 128 + w * 16 + (lane >> 2);
        #pragma unroll
        for (int nd = 0; nd < 8; nd++) {
            const int d0 = nd * 8 + (lane & 3) * 2;
            *(float2*)&out[((size_t)b * TT + tr0) * EE + h * SS + d0] =
                make_float2(o_fr[grp][nd][0] * inv0, o_fr[grp][nd][1] * inv0);
            *(float2*)&out[((size_t)b * TT + tr0 + 8) * EE + h * SS + d0] =
                make_float2(o_fr[grp][nd][2] * inv1, o_fr[grp][nd][3] * inv1);
        }
    }
}

// ---------------------------------------------------------------------------
extern "C" void kernel_launch(void* const* d_in, const int* in_sizes, int n_in,
                              void* d_out, int out_size)
{
    const float* x  = (const float*)d_in[0];
    const float* wq = (const float*)d_in[1];
    const float* wk = (const float*)d_in[2];
    const float* wv = (const float*)d_in[3];
    float* out = (float*)d_out;

    cudaFuncSetAttribute(attn_mma_kernel,
                         cudaFuncAttributeMaxDynamicSharedMemorySize, ATT_SMEM_BYTES);

    convert_kernel<<<(NTOT4 + 255) / 256, 256>>>(x, wq, wk, wv);
    qkv_mma_kernel<<<dim3(NN / 128, EE / 128, 3), 256>>>();
    attn_mma_kernel<<<dim3(CC, BB * HH), 256, ATT_SMEM_BYTES>>>(out);
}

// round 15
// speedup vs baseline: 1.0735x; 1.0735x over previous
#include <cuda_runtime.h>
#include <cuda_bf16.h>

// Problem constants
#define BB 2
#define TT 4096
#define EE 768
#define HH 12
#define SS 64
#define WW 256
#define CC 16
#define NN (BB * TT)   // 8192

// ---------------------------------------------------------------------------
// Packed split-bf16 scratch (device globals: allocation-free)
// Each uint32 = bf16(hi) in low 16 bits | bf16(residual) in high 16 bits.
// ---------------------------------------------------------------------------
__device__ unsigned g_xp[(size_t)NN * EE];
__device__ unsigned g_wp[(size_t)3 * EE * EE];
__device__ unsigned g_qp[(size_t)BB * HH * TT * SS];   // [b][h][t][d]
__device__ unsigned g_kp[(size_t)BB * HH * TT * SS];
__device__ unsigned g_vp[(size_t)BB * HH * TT * SS];

// ---------------------------------------------------------------------------
// Helpers
// ---------------------------------------------------------------------------
__device__ __forceinline__ unsigned pack2bf(float lo_elem, float hi_elem) {
    unsigned r;
    asm("cvt.rn.bf16x2.f32 %0, %1, %2;" : "=r"(r) : "f"(hi_elem), "f"(lo_elem));
    return r;
}
__device__ __forceinline__ unsigned pack_split(float v) {
    float hf = __bfloat162float(__float2bfloat16(v));
    return pack2bf(v, v - hf);   // low = hi-part, high = residual
}
__device__ __forceinline__ unsigned smaddr(const void* p) {
    return (unsigned)__cvta_generic_to_shared(p);
}
__device__ __forceinline__ void ldm_x4(unsigned a, unsigned& r0, unsigned& r1,
                                       unsigned& r2, unsigned& r3) {
    asm volatile("ldmatrix.sync.aligned.m8n8.x4.shared.b16 {%0,%1,%2,%3},[%4];"
                 : "=r"(r0), "=r"(r1), "=r"(r2), "=r"(r3) : "r"(a));
}
__device__ __forceinline__ void ldm_x4t(unsigned a, unsigned& r0, unsigned& r1,
                                        unsigned& r2, unsigned& r3) {
    asm volatile("ldmatrix.sync.aligned.m8n8.x4.trans.shared.b16 {%0,%1,%2,%3},[%4];"
                 : "=r"(r0), "=r"(r1), "=r"(r2), "=r"(r3) : "r"(a));
}
__device__ __forceinline__ void mma_bf16(float* d, const unsigned* a,
                                         unsigned b0, unsigned b1) {
    asm volatile(
        "mma.sync.aligned.m16n8k16.row.col.f32.bf16.bf16.f32 "
        "{%0,%1,%2,%3},{%4,%5,%6,%7},{%8,%9},{%0,%1,%2,%3};"
        : "+f"(d[0]), "+f"(d[1]), "+f"(d[2]), "+f"(d[3])
        : "r"(a[0]), "r"(a[1]), "r"(a[2]), "r"(a[3]), "r"(b0), "r"(b1));
}
// Truncated split of fp32: hi = upper 16 bits (exact truncation to bf16),
// residual = v - hi (exact in fp32).
__device__ __forceinline__ float trunc_resid(float v) {
    unsigned bits = __float_as_uint(v) & 0xFFFF0000u;
    return v - __uint_as_float(bits);
}

// ---------------------------------------------------------------------------
// Pass 0: fp32 -> packed split-bf16 for x and the three weights, one launch.
// ---------------------------------------------------------------------------
#define NX4 (NN * EE / 4)
#define NW4 (EE * EE / 4)
#define NTOT4 (NX4 + 3 * NW4)

__global__ __launch_bounds__(256) void convert_kernel(
    const float* __restrict__ x,  const float* __restrict__ wq,
    const float* __restrict__ wk, const float* __restrict__ wv)
{
    int i = blockIdx.x * 256 + threadIdx.x;
    if (i >= NTOT4) return;
    const float4* src;
    unsigned* dstbase;
    int j;
    if (i < NX4)                  { src = (const float4*)x;  dstbase = g_xp;              j = i; }
    else if (i < NX4 + NW4)       { src = (const float4*)wq; dstbase = g_wp;              j = i - NX4; }
    else if (i < NX4 + 2 * NW4)   { src = (const float4*)wk; dstbase = g_wp + EE * EE;     j = i - NX4 - NW4; }
    else                          { src = (const float4*)wv; dstbase = g_wp + 2 * EE * EE; j = i - NX4 - 2 * NW4; }
    float4 v = src[j];
    uint4 o;
    o.x = pack_split(v.x); o.y = pack_split(v.y);
    o.z = pack_split(v.z); o.w = pack_split(v.w);
    ((uint4*)dstbase)[j] = o;
}

// ---------------------------------------------------------------------------
// Pass 1: Q/K/V = x @ W^T via mma.sync bf16, split accumulation (3 mma).
// 128x128 tile, k-step 16, 256 threads = 8 warps (2x4), warp tile 64x32.
// (unchanged from the 473us champion: 24KB static smem, register prefetch)
// ---------------------------------------------------------------------------
#define QST 24

__global__ __launch_bounds__(256) void qkv_mma_kernel()
{
    __shared__ __nv_bfloat16 Ah[128 * QST], Al[128 * QST];
    __shared__ __nv_bfloat16 Bh[128 * QST], Bl[128 * QST];

    const int which = blockIdx.z;
    const unsigned* wp = g_wp + (size_t)which * EE * EE;
    unsigned* dst = (which == 0) ? g_qp : (which == 1) ? g_kp : g_vp;
    const float scale = (which == 0) ? 0.125f : 1.0f;

    const int rowBase = blockIdx.x * 128;
    const int colBase = blockIdx.y * 128;
    const int t    = threadIdx.x;
    const int lane = t & 31;
    const int w    = t >> 5;
    const int wm   = (w >> 2) * 64;
    const int wn   = (w & 3) * 32;

    float acc[4][4][4];
    #pragma unroll
    for (int mt = 0; mt < 4; mt++)
        #pragma unroll
        for (int nt = 0; nt < 4; nt++)
            #pragma unroll
            for (int e = 0; e < 4; e++) acc[mt][nt][e] = 0.0f;

    uint4 pa[2], pb[2];
    // prologue load (k0 = 0)
    #pragma unroll
    for (int j = 0; j < 2; j++) {
        const int s   = t + j * 256;
        const int row = s >> 2;
        const int q4  = (s & 3) * 4;
        pa[j] = *(const uint4*)&g_xp[(size_t)(rowBase + row) * EE + q4];
        pb[j] = *(const uint4*)&wp  [(size_t)(colBase + row) * EE + q4];
    }

    for (int k0 = 0; k0 < EE; k0 += 16) {
        __syncthreads();
        #pragma unroll
        for (int j = 0; j < 2; j++) {
            const int s   = t + j * 256;
            const int row = s >> 2;
            const int q4  = (s & 3) * 4;
            *(unsigned*)&Ah[row * QST + q4]     = __byte_perm(pa[j].x, pa[j].y, 0x5410);
            *(unsigned*)&Ah[row * QST + q4 + 2] = __byte_perm(pa[j].z, pa[j].w, 0x5410);
            *(unsigned*)&Al[row * QST + q4]     = __byte_perm(pa[j].x, pa[j].y, 0x7632);
            *(unsigned*)&Al[row * QST + q4 + 2] = __byte_perm(pa[j].z, pa[j].w, 0x7632);
            *(unsigned*)&Bh[row * QST + q4]     = __byte_perm(pb[j].x, pb[j].y, 0x5410);
            *(unsigned*)&Bh[row * QST + q4 + 2] = __byte_perm(pb[j].z, pb[j].w, 0x5410);
            *(unsigned*)&Bl[row * QST + q4]     = __byte_perm(pb[j].x, pb[j].y, 0x7632);
            *(unsigned*)&Bl[row * QST + q4 + 2] = __byte_perm(pb[j].z, pb[j].w, 0x7632);
        }
        __syncthreads();

        if (k0 + 16 < EE) {
            #pragma unroll
            for (int j = 0; j < 2; j++) {
                const int s   = t + j * 256;
                const int row = s >> 2;
                const int q4  = (s & 3) * 4;
                pa[j] = *(const uint4*)&g_xp[(size_t)(rowBase + row) * EE + k0 + 16 + q4];
                pb[j] = *(const uint4*)&wp  [(size_t)(colBase + row) * EE + k0 + 16 + q4];
            }
        }

        unsigned ah[4][4], al[4][4], bh[2][4], bl[2][4];
        #pragma unroll
        for (int mt = 0; mt < 4; mt++) {
            const int off = (wm + mt * 16 + (lane & 15)) * QST + ((lane >> 4) << 3);
            ldm_x4(smaddr(&Ah[off]), ah[mt][0], ah[mt][1], ah[mt][2], ah[mt][3]);
            ldm_x4(smaddr(&Al[off]), al[mt][0], al[mt][1], al[mt][2], al[mt][3]);
        }
        #pragma unroll
        for (int g = 0; g < 2; g++) {
            const int off = (wn + g * 16 + ((lane >> 4) << 3) + (lane & 7)) * QST
                          + (((lane >> 3) & 1) << 3);
            ldm_x4(smaddr(&Bh[off]), bh[g][0], bh[g][1], bh[g][2], bh[g][3]);
            ldm_x4(smaddr(&Bl[off]), bl[g][0], bl[g][1], bl[g][2], bl[g][3]);
        }
        #pragma unroll
        for (int mt = 0; mt < 4; mt++)
            #pragma unroll
            for (int nt = 0; nt < 4; nt++) {
                const int g  = nt >> 1;
                const int hb = (nt & 1) * 2;
                mma_bf16(acc[mt][nt], ah[mt], bh[g][hb], bh[g][hb + 1]);
                mma_bf16(acc[mt][nt], al[mt], bh[g][hb], bh[g][hb + 1]);
                mma_bf16(acc[mt][nt], ah[mt], bl[g][hb], bl[g][hb + 1]);
            }
    }

    // epilogue: pack split + store [b][h][t][d]
    #pragma unroll
    for (int mt = 0; mt < 4; mt++) {
        const int rg0 = rowBase + wm + mt * 16 + (lane >> 2);
        #pragma unroll
        for (int nt = 0; nt < 4; nt++) {
            const int jc = colBase + wn + nt * 8 + (lane & 3) * 2;
            const int h  = jc >> 6;
            const int d  = jc & 63;
            #pragma unroll
            for (int rh = 0; rh < 2; rh++) {
                const int rg = rg0 + rh * 8;
                const int bb = rg >> 12;
                const int tt = rg & (TT - 1);
                uint2 pv;
                pv.x = pack_split(acc[mt][nt][rh * 2 + 0] * scale);
                pv.y = pack_split(acc[mt][nt][rh * 2 + 1] * scale);
                *(uint2*)&dst[(((size_t)(bb * HH + h) * TT) + tt) * SS + d] = pv;
            }
        }
    }
}

// ---------------------------------------------------------------------------
// Pass 2: fused flash attention, all-mma. Block = 128 q x (b,h); 8 warps,
// warp = 16 q rows x 128 keys per tile. 6 key tiles of 128. Split-bf16.
// (champion structure; P repack via exact truncation + residual)
// ---------------------------------------------------------------------------
#define KST 72
#define ATT_SMEM_ELEMS (4 * 128 * KST)
#define ATT_SMEM_BYTES (ATT_SMEM_ELEMS * 2)

__global__ __launch_bounds__(256) void attn_mma_kernel(float* __restrict__ out)
{
    extern __shared__ __nv_bfloat16 sm[];
    __nv_bfloat16* Kh = sm;
    __nv_bfloat16* Kl = sm + 128 * KST;
    __nv_bfloat16* Vh = sm + 2 * 128 * KST;
    __nv_bfloat16* Vl = sm + 3 * 128 * KST;

    const int c    = blockIdx.x >> 1;
    const int half = blockIdx.x & 1;
    const int bh   = blockIdx.y;
    const int b = bh / HH;
    const int h = bh % HH;

    const int t    = threadIdx.x;
    const int lane = t & 31;
    const int w    = t >> 5;

    // ---- stage Q (128x64) into Kh/Kl, build register-resident Q frags ----
    {
        const unsigned* qb = g_qp + ((size_t)bh * TT + c * WW + half * 128) * SS;
        #pragma unroll
        for (int i = 0; i < 8; i++) {
            const int s   = t + i * 256;
            const int row = s >> 4;
            const int q4  = (s & 15) * 4;
            uint4 v = *(const uint4*)&qb[row * SS + q4];
            *(unsigned*)&Kh[row * KST + q4]     = __byte_perm(v.x, v.y, 0x5410);
            *(unsigned*)&Kh[row * KST + q4 + 2] = __byte_perm(v.z, v.w, 0x5410);
            *(unsigned*)&Kl[row * KST + q4]     = __byte_perm(v.x, v.y, 0x7632);
            *(unsigned*)&Kl[row * KST + q4 + 2] = __byte_perm(v.z, v.w, 0x7632);
        }
    }
    __syncthreads();

    unsigned qh[4][4], ql[4][4];
    #pragma unroll
    for (int kt = 0; kt < 4; kt++) {
        const int off = (w * 16 + (lane & 15)) * KST + kt * 16 + ((lane >> 4) << 3);
        ldm_x4(smaddr(&Kh[off]), qh[kt][0], qh[kt][1], qh[kt][2], qh[kt][3]);
        ldm_x4(smaddr(&Kl[off]), ql[kt][0], ql[kt][1], ql[kt][2], ql[kt][3]);
    }

    float m0 = -1e30f, m1 = -1e30f, l0 = 0.0f, l1 = 0.0f;
    float o_fr[8][4];
    #pragma unroll
    for (int nd = 0; nd < 8; nd++)
        #pragma unroll
        for (int e = 0; e < 4; e++) o_fr[nd][e] = 0.0f;

    const int xq0 = half * 128 + w * 16 + (lane >> 2);  // row of c0/c1

    for (int nt = 0; nt < 6; nt++) {
        const int kc = c - 1 + (nt >> 1);
        const bool valid = (kc >= 0) && (kc < CC);

        float s_fr[16][4];

        if (valid) {
            const int y0 = (nt & 1) * 128;
            const unsigned* kb = g_kp + ((size_t)bh * TT + kc * WW + y0) * SS;
            const unsigned* vb = g_vp + ((size_t)bh * TT + kc * WW + y0) * SS;

            __syncthreads();   // everyone done with smem from prior tile / Q frags
            #pragma unroll
            for (int i = 0; i < 8; i++) {
                const int s   = t + i * 256;
                const int row = s >> 4;
                const int q4  = (s & 15) * 4;
                uint4 kv = *(const uint4*)&kb[row * SS + q4];
                uint4 vv = *(const uint4*)&vb[row * SS + q4];
                *(unsigned*)&Kh[row * KST + q4]     = __byte_perm(kv.x, kv.y, 0x5410);
                *(unsigned*)&Kh[row * KST + q4 + 2] = __byte_perm(kv.z, kv.w, 0x5410);
                *(unsigned*)&Kl[row * KST + q4]     = __byte_perm(kv.x, kv.y, 0x7632);
                *(unsigned*)&Kl[row * KST + q4 + 2] = __byte_perm(kv.z, kv.w, 0x7632);
                *(unsigned*)&Vh[row * KST + q4]     = __byte_perm(vv.x, vv.y, 0x5410);
                *(unsigned*)&Vh[row * KST + q4 + 2] = __byte_perm(vv.z, vv.w, 0x5410);
                *(unsigned*)&Vl[row * KST + q4]     = __byte_perm(vv.x, vv.y, 0x7632);
                *(unsigned*)&Vl[row * KST + q4 + 2] = __byte_perm(vv.z, vv.w, 0x7632);
            }
            __syncthreads();

            #pragma unroll
            for (int n = 0; n < 16; n++)
                #pragma unroll
                for (int e = 0; e < 4; e++) s_fr[n][e] = 0.0f;

            #pragma unroll
            for (int kt = 0; kt < 4; kt++) {
                #pragma unroll
                for (int g = 0; g < 8; g++) {
                    unsigned kbf[4], klf[4];
                    const int off = (g * 16 + ((lane >> 4) << 3) + (lane & 7)) * KST
                                  + kt * 16 + (((lane >> 3) & 1) << 3);
                    ldm_x4(smaddr(&Kh[off]), kbf[0], kbf[1], kbf[2], kbf[3]);
                    ldm_x4(smaddr(&Kl[off]), klf[0], klf[1], klf[2], klf[3]);
                    #pragma unroll
                    for (int h2 = 0; h2 < 2; h2++) {
                        const int n = g * 2 + h2;
                        mma_bf16(s_fr[n], qh[kt], kbf[h2 * 2], kbf[h2 * 2 + 1]);
                        mma_bf16(s_fr[n], ql[kt], kbf[h2 * 2], kbf[h2 * 2 + 1]);
                        mma_bf16(s_fr[n], qh[kt], klf[h2 * 2], klf[h2 * 2 + 1]);
                    }
                }
            }
        } else {
            // zero-padded neighbor chunk: score 0, boundary mask -1e30
            #pragma unroll
            for (int n = 0; n < 16; n++) {
                const int jg = nt * 128 + n * 8 + (lane & 3) * 2;
                #pragma unroll
                for (int e = 0; e < 4; e++) {
                    const int xq = xq0 + (e >> 1) * 8;
                    const int j  = jg + (e & 1);
                    const bool msk = (c == 0) ? (j < WW - xq)
                                              : (j >= 3 * WW - 1 - xq);
                    s_fr[n][e] = msk ? -1e30f : 0.0f;
                }
            }
        }

        // ---- online softmax on fragments ----
        float rm0 = -1e30f, rm1 = -1e30f;
        #pragma unroll
        for (int n = 0; n < 16; n++) {
            rm0 = fmaxf(rm0, fmaxf(s_fr[n][0], s_fr[n][1]));
            rm1 = fmaxf(rm1, fmaxf(s_fr[n][2], s_fr[n][3]));
        }
        #pragma unroll
        for (int off = 1; off <= 2; off <<= 1) {
            rm0 = fmaxf(rm0, __shfl_xor_sync(0xFFFFFFFFu, rm0, off));
            rm1 = fmaxf(rm1, __shfl_xor_sync(0xFFFFFFFFu, rm1, off));
        }
        const float mn0 = fmaxf(m0, rm0);
        const float mn1 = fmaxf(m1, rm1);
        const float al0 = __expf(m0 - mn0);
        const float al1 = __expf(m1 - mn1);
        float rs0 = 0.0f, rs1 = 0.0f;
        #pragma unroll
        for (int n = 0; n < 16; n++) {
            s_fr[n][0] = __expf(s_fr[n][0] - mn0);
            s_fr[n][1] = __expf(s_fr[n][1] - mn0);
            s_fr[n][2] = __expf(s_fr[n][2] - mn1);
            s_fr[n][3] = __expf(s_fr[n][3] - mn1);
            rs0 += s_fr[n][0] + s_fr[n][1];
            rs1 += s_fr[n][2] + s_fr[n][3];
        }
        #pragma unroll
        for (int off = 1; off <= 2; off <<= 1) {
            rs0 += __shfl_xor_sync(0xFFFFFFFFu, rs0, off);
            rs1 += __shfl_xor_sync(0xFFFFFFFFu, rs1, off);
        }
        l0 = l0 * al0 + rs0;  m0 = mn0;
        l1 = l1 * al1 + rs1;  m1 = mn1;
        #pragma unroll
        for (int nd = 0; nd < 8; nd++) {
            o_fr[nd][0] *= al0; o_fr[nd][1] *= al0;
            o_fr[nd][2] *= al1; o_fr[nd][3] *= al1;
        }

        if (valid) {
            // ---- O += P @ V (truncated split of P; 3 mma) ----
            #pragma unroll
            for (int ktj = 0; ktj < 8; ktj++) {
                const float* pe = s_fr[2 * ktj];
                const float* po = s_fr[2 * ktj + 1];
                unsigned pah[4], pal[4];
                pah[0] = __byte_perm(__float_as_uint(pe[0]), __float_as_uint(pe[1]), 0x7632);
                pah[1] = __byte_perm(__float_as_uint(pe[2]), __float_as_uint(pe[3]), 0x7632);
                pah[2] = __byte_perm(__float_as_uint(po[0]), __float_as_uint(po[1]), 0x7632);
                pah[3] = __byte_perm(__float_as_uint(po[2]), __float_as_uint(po[3]), 0x7632);
                pal[0] = pack2bf(trunc_resid(pe[0]), trunc_resid(pe[1]));
                pal[1] = pack2bf(trunc_resid(pe[2]), trunc_resid(pe[3]));
                pal[2] = pack2bf(trunc_resid(po[0]), trunc_resid(po[1]));
                pal[3] = pack2bf(trunc_resid(po[2]), trunc_resid(po[3]));

                #pragma unroll
                for (int g = 0; g < 4; g++) {
                    unsigned vbf[4], vlf[4];
                    const int off = (ktj * 16 + (lane & 15)) * KST
                                  + g * 16 + ((lane >> 4) << 3);
                    ldm_x4t(smaddr(&Vh[off]), vbf[0], vbf[1], vbf[2], vbf[3]);
                    ldm_x4t(smaddr(&Vl[off]), vlf[0], vlf[1], vlf[2], vlf[3]);
                    #pragma unroll
                    for (int h2 = 0; h2 < 2; h2++) {
                        const int nd = g * 2 + h2;
                        mma_bf16(o_fr[nd], pah, vbf[h2 * 2], vbf[h2 * 2 + 1]);
                        mma_bf16(o_fr[nd], pal, vbf[h2 * 2], vbf[h2 * 2 + 1]);
                        mma_bf16(o_fr[nd], pah, vlf[h2 * 2], vlf[h2 * 2 + 1]);
                    }
                }
            }
        }
    }

    // ---- epilogue: normalize + store fp32 ----
    const float inv0 = 1.0f / l0;
    const float inv1 = 1.0f / l1;
    const int tr0 = c * WW + half * 128 + w * 16 + (lane >> 2);
    #pragma unroll
    for (int nd = 0; nd < 8; nd++) {
        const int d0 = nd * 8 + (lane & 3) * 2;
        *(float2*)&out[((size_t)b * TT + tr0) * EE + h * SS + d0] =
            make_float2(o_fr[nd][0] * inv0, o_fr[nd][1] * inv0);
        *(float2*)&out[((size_t)b * TT + tr0 + 8) * EE + h * SS + d0] =
            make_float2(o_fr[nd][2] * inv1, o_fr[nd][3] * inv1);
    }
}

// ---------------------------------------------------------------------------
extern "C" void kernel_launch(void* const* d_in, const int* in_sizes, int n_in,
                              void* d_out, int out_size)
{
    const float* x  = (const float*)d_in[0];
    const float* wq = (const float*)d_in[1];
    const float* wk = (const float*)d_in[2];
    const float* wv = (const float*)d_in[3];
    float* out = (float*)d_out;

    cudaFuncSetAttribute(attn_mma_kernel,
                         cudaFuncAttributeMaxDynamicSharedMemorySize, ATT_SMEM_BYTES);

    convert_kernel<<<(NTOT4 + 255) / 256, 256>>>(x, wq, wk, wv);
    qkv_mma_kernel<<<dim3(NN / 128, EE / 128, 3), 256>>>();
    attn_mma_kernel<<<dim3(2 * CC, BB * HH), 256, ATT_SMEM_BYTES>>>(out);
}

// round 17
// speedup vs baseline: 1.0994x; 1.0241x over previous
#include <cuda_runtime.h>
#include <cuda_bf16.h>

// Problem constants
#define BB 2
#define TT 4096
#define EE 768
#define HH 12
#define SS 64
#define WW 256
#define CC 16
#define NN (BB * TT)   // 8192

// ---------------------------------------------------------------------------
// Packed split-bf16 scratch (device globals: allocation-free)
// Each uint32 = bf16(hi) in low 16 bits | bf16(residual) in high 16 bits.
// Q is stored pre-scaled by 1/sqrt(64) * log2(e) so attn softmax runs in the
// log2 domain (bare EX2, no multiply inside the exp).
// ---------------------------------------------------------------------------
__device__ unsigned g_xp[(size_t)NN * EE];
__device__ unsigned g_wp[(size_t)3 * EE * EE];
__device__ unsigned g_qp[(size_t)BB * HH * TT * SS];   // [b][h][t][d]
__device__ unsigned g_kp[(size_t)BB * HH * TT * SS];
__device__ unsigned g_vp[(size_t)BB * HH * TT * SS];

// ---------------------------------------------------------------------------
// Helpers
// ---------------------------------------------------------------------------
__device__ __forceinline__ unsigned pack2bf(float lo_elem, float hi_elem) {
    unsigned r;
    asm("cvt.rn.bf16x2.f32 %0, %1, %2;" : "=r"(r) : "f"(hi_elem), "f"(lo_elem));
    return r;
}
__device__ __forceinline__ unsigned pack_split(float v) {
    float hf = __bfloat162float(__float2bfloat16(v));
    return pack2bf(v, v - hf);   // low = hi-part, high = residual
}
__device__ __forceinline__ unsigned smaddr(const void* p) {
    return (unsigned)__cvta_generic_to_shared(p);
}
__device__ __forceinline__ void ldm_x4(unsigned a, unsigned& r0, unsigned& r1,
                                       unsigned& r2, unsigned& r3) {
    asm volatile("ldmatrix.sync.aligned.m8n8.x4.shared.b16 {%0,%1,%2,%3},[%4];"
                 : "=r"(r0), "=r"(r1), "=r"(r2), "=r"(r3) : "r"(a));
}
__device__ __forceinline__ void ldm_x4t(unsigned a, unsigned& r0, unsigned& r1,
                                        unsigned& r2, unsigned& r3) {
    asm volatile("ldmatrix.sync.aligned.m8n8.x4.trans.shared.b16 {%0,%1,%2,%3},[%4];"
                 : "=r"(r0), "=r"(r1), "=r"(r2), "=r"(r3) : "r"(a));
}
__device__ __forceinline__ void mma_bf16(float* d, const unsigned* a,
                                         unsigned b0, unsigned b1) {
    asm volatile(
        "mma.sync.aligned.m16n8k16.row.col.f32.bf16.bf16.f32 "
        "{%0,%1,%2,%3},{%4,%5,%6,%7},{%8,%9},{%0,%1,%2,%3};"
        : "+f"(d[0]), "+f"(d[1]), "+f"(d[2]), "+f"(d[3])
        : "r"(a[0]), "r"(a[1]), "r"(a[2]), "r"(a[3]), "r"(b0), "r"(b1));
}
// Truncated split of fp32: hi = upper 16 bits (exact truncation to bf16),
// residual = v - hi (exact in fp32).
__device__ __forceinline__ float trunc_resid(float v) {
    unsigned bits = __float_as_uint(v) & 0xFFFF0000u;
    return v - __uint_as_float(bits);
}
// Fast exp2 (scores arrive pre-scaled by log2e)
__device__ __forceinline__ float ex2(float v) {
    float r;
    asm("ex2.approx.ftz.f32 %0, %1;" : "=f"(r) : "f"(v));
    return r;
}

// ---------------------------------------------------------------------------
// Pass 0: fp32 -> packed split-bf16 for x and the three weights, one launch.
// ---------------------------------------------------------------------------
#define NX4 (NN * EE / 4)
#define NW4 (EE * EE / 4)
#define NTOT4 (NX4 + 3 * NW4)

__global__ __launch_bounds__(256) void convert_kernel(
    const float* __restrict__ x,  const float* __restrict__ wq,
    const float* __restrict__ wk, const float* __restrict__ wv)
{
    int i = blockIdx.x * 256 + threadIdx.x;
    if (i >= NTOT4) return;
    const float4* src;
    unsigned* dstbase;
    int j;
    if (i < NX4)                  { src = (const float4*)x;  dstbase = g_xp;              j = i; }
    else if (i < NX4 + NW4)       { src = (const float4*)wq; dstbase = g_wp;              j = i - NX4; }
    else if (i < NX4 + 2 * NW4)   { src = (const float4*)wk; dstbase = g_wp + EE * EE;     j = i - NX4 - NW4; }
    else                          { src = (const float4*)wv; dstbase = g_wp + 2 * EE * EE; j = i - NX4 - 2 * NW4; }
    float4 v = src[j];
    uint4 o;
    o.x = pack_split(v.x); o.y = pack_split(v.y);
    o.z = pack_split(v.z); o.w = pack_split(v.w);
    ((uint4*)dstbase)[j] = o;
}

// ---------------------------------------------------------------------------
// Pass 1: Q/K/V = x @ W^T via mma.sync bf16, split accumulation (3 mma).
// 128x128 tile, k-step 16, 256 threads = 8 warps (2x4), warp tile 64x32.
// (champion structure: 24KB static smem, register prefetch)
// Q scale folds in log2(e) for the log2-domain softmax downstream.
// ---------------------------------------------------------------------------
#define QST 24
#define QSCALE 0.18033688f   // 0.125 * log2(e)

__global__ __launch_bounds__(256) void qkv_mma_kernel()
{
    __shared__ __nv_bfloat16 Ah[128 * QST], Al[128 * QST];
    __shared__ __nv_bfloat16 Bh[128 * QST], Bl[128 * QST];

    const int which = blockIdx.z;
    const unsigned* wp = g_wp + (size_t)which * EE * EE;
    unsigned* dst = (which == 0) ? g_qp : (which == 1) ? g_kp : g_vp;
    const float scale = (which == 0) ? QSCALE : 1.0f;

    const int rowBase = blockIdx.x * 128;
    const int colBase = blockIdx.y * 128;
    const int t    = threadIdx.x;
    const int lane = t & 31;
    const int w    = t >> 5;
    const int wm   = (w >> 2) * 64;
    const int wn   = (w & 3) * 32;

    float acc[4][4][4];
    #pragma unroll
    for (int mt = 0; mt < 4; mt++)
        #pragma unroll
        for (int nt = 0; nt < 4; nt++)
            #pragma unroll
            for (int e = 0; e < 4; e++) acc[mt][nt][e] = 0.0f;

    uint4 pa[2], pb[2];
    // prologue load (k0 = 0)
    #pragma unroll
    for (int j = 0; j < 2; j++) {
        const int s   = t + j * 256;
        const int row = s >> 2;
        const int q4  = (s & 3) * 4;
        pa[j] = *(const uint4*)&g_xp[(size_t)(rowBase + row) * EE + q4];
        pb[j] = *(const uint4*)&wp  [(size_t)(colBase + row) * EE + q4];
    }

    for (int k0 = 0; k0 < EE; k0 += 16) {
        __syncthreads();
        #pragma unroll
        for (int j = 0; j < 2; j++) {
            const int s   = t + j * 256;
            const int row = s >> 2;
            const int q4  = (s & 3) * 4;
            *(uint2*)&Ah[row * QST + q4] =
                make_uint2(__byte_perm(pa[j].x, pa[j].y, 0x5410), __byte_perm(pa[j].z, pa[j].w, 0x5410));
            *(uint2*)&Al[row * QST + q4] =
                make_uint2(__byte_perm(pa[j].x, pa[j].y, 0x7632), __byte_perm(pa[j].z, pa[j].w, 0x7632));
            *(uint2*)&Bh[row * QST + q4] =
                make_uint2(__byte_perm(pb[j].x, pb[j].y, 0x5410), __byte_perm(pb[j].z, pb[j].w, 0x5410));
            *(uint2*)&Bl[row * QST + q4] =
                make_uint2(__byte_perm(pb[j].x, pb[j].y, 0x7632), __byte_perm(pb[j].z, pb[j].w, 0x7632));
        }
        __syncthreads();

        if (k0 + 16 < EE) {
            #pragma unroll
            for (int j = 0; j < 2; j++) {
                const int s   = t + j * 256;
                const int row = s >> 2;
                const int q4  = (s & 3) * 4;
                pa[j] = *(const uint4*)&g_xp[(size_t)(rowBase + row) * EE + k0 + 16 + q4];
                pb[j] = *(const uint4*)&wp  [(size_t)(colBase + row) * EE + k0 + 16 + q4];
            }
        }

        unsigned ah[4][4], al[4][4], bh[2][4], bl[2][4];
        #pragma unroll
        for (int mt = 0; mt < 4; mt++) {
            const int off = (wm + mt * 16 + (lane & 15)) * QST + ((lane >> 4) << 3);
            ldm_x4(smaddr(&Ah[off]), ah[mt][0], ah[mt][1], ah[mt][2], ah[mt][3]);
            ldm_x4(smaddr(&Al[off]), al[mt][0], al[mt][1], al[mt][2], al[mt][3]);
        }
        #pragma unroll
        for (int g = 0; g < 2; g++) {
            const int off = (wn + g * 16 + ((lane >> 4) << 3) + (lane & 7)) * QST
                          + (((lane >> 3) & 1) << 3);
            ldm_x4(smaddr(&Bh[off]), bh[g][0], bh[g][1], bh[g][2], bh[g][3]);
            ldm_x4(smaddr(&Bl[off]), bl[g][0], bl[g][1], bl[g][2], bl[g][3]);
        }
        #pragma unroll
        for (int mt = 0; mt < 4; mt++)
            #pragma unroll
            for (int nt = 0; nt < 4; nt++) {
                const int g  = nt >> 1;
                const int hb = (nt & 1) * 2;
                mma_bf16(acc[mt][nt], ah[mt], bh[g][hb], bh[g][hb + 1]);
                mma_bf16(acc[mt][nt], al[mt], bh[g][hb], bh[g][hb + 1]);
                mma_bf16(acc[mt][nt], ah[mt], bl[g][hb], bl[g][hb + 1]);
            }
    }

    // epilogue: pack split + store [b][h][t][d]
    #pragma unroll
    for (int mt = 0; mt < 4; mt++) {
        const int rg0 = rowBase + wm + mt * 16 + (lane >> 2);
        #pragma unroll
        for (int nt = 0; nt < 4; nt++) {
            const int jc = colBase + wn + nt * 8 + (lane & 3) * 2;
            const int h  = jc >> 6;
            const int d  = jc & 63;
            #pragma unroll
            for (int rh = 0; rh < 2; rh++) {
                const int rg = rg0 + rh * 8;
                const int bb = rg >> 12;
                const int tt = rg & (TT - 1);
                uint2 pv;
                pv.x = pack_split(acc[mt][nt][rh * 2 + 0] * scale);
                pv.y = pack_split(acc[mt][nt][rh * 2 + 1] * scale);
                *(uint2*)&dst[(((size_t)(bb * HH + h) * TT) + tt) * SS + d] = pv;
            }
        }
    }
}

// ---------------------------------------------------------------------------
// Pass 2: fused flash attention, all-mma. Block = 128 q x (b,h); 8 warps,
// warp = 16 q rows x 128 keys per tile. 6 key tiles of 128. Split-bf16.
// Softmax in log2 domain (Q pre-scaled by log2e): bare EX2, no mul.
// ---------------------------------------------------------------------------
#define KST 72
#define ATT_SMEM_ELEMS (4 * 128 * KST)
#define ATT_SMEM_BYTES (ATT_SMEM_ELEMS * 2)

__global__ __launch_bounds__(256) void attn_mma_kernel(float* __restrict__ out)
{
    extern __shared__ __nv_bfloat16 sm[];
    __nv_bfloat16* Kh = sm;
    __nv_bfloat16* Kl = sm + 128 * KST;
    __nv_bfloat16* Vh = sm + 2 * 128 * KST;
    __nv_bfloat16* Vl = sm + 3 * 128 * KST;

    const int c    = blockIdx.x >> 1;
    const int half = blockIdx.x & 1;
    const int bh   = blockIdx.y;
    const int b = bh / HH;
    const int h = bh % HH;

    const int t    = threadIdx.x;
    const int lane = t & 31;
    const int w    = t >> 5;

    // ---- stage Q (128x64) into Kh/Kl, build register-resident Q frags ----
    {
        const unsigned* qb = g_qp + ((size_t)bh * TT + c * WW + half * 128) * SS;
        #pragma unroll
        for (int i = 0; i < 8; i++) {
            const int s   = t + i * 256;
            const int row = s >> 4;
            const int q4  = (s & 15) * 4;
            uint4 v = *(const uint4*)&qb[row * SS + q4];
            *(uint2*)&Kh[row * KST + q4] =
                make_uint2(__byte_perm(v.x, v.y, 0x5410), __byte_perm(v.z, v.w, 0x5410));
            *(uint2*)&Kl[row * KST + q4] =
                make_uint2(__byte_perm(v.x, v.y, 0x7632), __byte_perm(v.z, v.w, 0x7632));
        }
    }
    __syncthreads();

    unsigned qh[4][4], ql[4][4];
    #pragma unroll
    for (int kt = 0; kt < 4; kt++) {
        const int off = (w * 16 + (lane & 15)) * KST + kt * 16 + ((lane >> 4) << 3);
        ldm_x4(smaddr(&Kh[off]), qh[kt][0], qh[kt][1], qh[kt][2], qh[kt][3]);
        ldm_x4(smaddr(&Kl[off]), ql[kt][0], ql[kt][1], ql[kt][2], ql[kt][3]);
    }

    float m0 = -1e30f, m1 = -1e30f, l0 = 0.0f, l1 = 0.0f;
    float o_fr[8][4];
    #pragma unroll
    for (int nd = 0; nd < 8; nd++)
        #pragma unroll
        for (int e = 0; e < 4; e++) o_fr[nd][e] = 0.0f;

    const int xq0 = half * 128 + w * 16 + (lane >> 2);  // row of c0/c1

    for (int nt = 0; nt < 6; nt++) {
        const int kc = c - 1 + (nt >> 1);
        const bool valid = (kc >= 0) && (kc < CC);

        float s_fr[16][4];

        if (valid) {
            const int y0 = (nt & 1) * 128;
            const unsigned* kb = g_kp + ((size_t)bh * TT + kc * WW + y0) * SS;
            const unsigned* vb = g_vp + ((size_t)bh * TT + kc * WW + y0) * SS;

            __syncthreads();   // everyone done with smem from prior tile / Q frags
            #pragma unroll
            for (int i = 0; i < 8; i++) {
                const int s   = t + i * 256;
                const int row = s >> 4;
                const int q4  = (s & 15) * 4;
                uint4 kv = *(const uint4*)&kb[row * SS + q4];
                uint4 vv = *(const uint4*)&vb[row * SS + q4];
                *(uint2*)&Kh[row * KST + q4] =
                    make_uint2(__byte_perm(kv.x, kv.y, 0x5410), __byte_perm(kv.z, kv.w, 0x5410));
                *(uint2*)&Kl[row * KST + q4] =
                    make_uint2(__byte_perm(kv.x, kv.y, 0x7632), __byte_perm(kv.z, kv.w, 0x7632));
                *(uint2*)&Vh[row * KST + q4] =
                    make_uint2(__byte_perm(vv.x, vv.y, 0x5410), __byte_perm(vv.z, vv.w, 0x5410));
                *(uint2*)&Vl[row * KST + q4] =
                    make_uint2(__byte_perm(vv.x, vv.y, 0x7632), __byte_perm(vv.z, vv.w, 0x7632));
            }
            __syncthreads();

            #pragma unroll
            for (int n = 0; n < 16; n++)
                #pragma unroll
                for (int e = 0; e < 4; e++) s_fr[n][e] = 0.0f;

            #pragma unroll
            for (int kt = 0; kt < 4; kt++) {
                #pragma unroll
                for (int g = 0; g < 8; g++) {
                    unsigned kbf[4], klf[4];
                    const int off = (g * 16 + ((lane >> 4) << 3) + (lane & 7)) * KST
                                  + kt * 16 + (((lane >> 3) & 1) << 3);
                    ldm_x4(smaddr(&Kh[off]), kbf[0], kbf[1], kbf[2], kbf[3]);
                    ldm_x4(smaddr(&Kl[off]), klf[0], klf[1], klf[2], klf[3]);
                    #pragma unroll
                    for (int h2 = 0; h2 < 2; h2++) {
                        const int n = g * 2 + h2;
                        mma_bf16(s_fr[n], qh[kt], kbf[h2 * 2], kbf[h2 * 2 + 1]);
                        mma_bf16(s_fr[n], ql[kt], kbf[h2 * 2], kbf[h2 * 2 + 1]);
                        mma_bf16(s_fr[n], qh[kt], klf[h2 * 2], klf[h2 * 2 + 1]);
                    }
                }
            }
        } else {
            // zero-padded neighbor chunk: score 0, boundary mask -1e30
            // (0 * log2e = 0, so the log2 domain leaves these unchanged)
            #pragma unroll
            for (int n = 0; n < 16; n++) {
                const int jg = nt * 128 + n * 8 + (lane & 3) * 2;
                #pragma unroll
                for (int e = 0; e < 4; e++) {
                    const int xq = xq0 + (e >> 1) * 8;
                    const int j  = jg + (e & 1);
                    const bool msk = (c == 0) ? (j < WW - xq)
                                              : (j >= 3 * WW - 1 - xq);
                    s_fr[n][e] = msk ? -1e30f : 0.0f;
                }
            }
        }

        // ---- online softmax on fragments (log2 domain: EX2 only) ----
        float rm0 = -1e30f, rm1 = -1e30f;
        #pragma unroll
        for (int n = 0; n < 16; n++) {
            rm0 = fmaxf(rm0, fmaxf(s_fr[n][0], s_fr[n][1]));
            rm1 = fmaxf(rm1, fmaxf(s_fr[n][2], s_fr[n][3]));
        }
        #pragma unroll
        for (int off = 1; off <= 2; off <<= 1) {
            rm0 = fmaxf(rm0, __shfl_xor_sync(0xFFFFFFFFu, rm0, off));
            rm1 = fmaxf(rm1, __shfl_xor_sync(0xFFFFFFFFu, rm1, off));
        }
        const float mn0 = fmaxf(m0, rm0);
        const float mn1 = fmaxf(m1, rm1);
        const float al0 = ex2(m0 - mn0);
        const float al1 = ex2(m1 - mn1);
        float rs0 = 0.0f, rs1 = 0.0f;
        #pragma unroll
        for (int n = 0; n < 16; n++) {
            s_fr[n][0] = ex2(s_fr[n][0] - mn0);
            s_fr[n][1] = ex2(s_fr[n][1] - mn0);
            s_fr[n][2] = ex2(s_fr[n][2] - mn1);
            s_fr[n][3] = ex2(s_fr[n][3] - mn1);
            rs0 += s_fr[n][0] + s_fr[n][1];
            rs1 += s_fr[n][2] + s_fr[n][3];
        }
        #pragma unroll
        for (int off = 1; off <= 2; off <<= 1) {
            rs0 += __shfl_xor_sync(0xFFFFFFFFu, rs0, off);
            rs1 += __shfl_xor_sync(0xFFFFFFFFu, rs1, off);
        }
        l0 = l0 * al0 + rs0;  m0 = mn0;
        l1 = l1 * al1 + rs1;  m1 = mn1;
        #pragma unroll
        for (int nd = 0; nd < 8; nd++) {
            o_fr[nd][0] *= al0; o_fr[nd][1] *= al0;
            o_fr[nd][2] *= al1; o_fr[nd][3] *= al1;
        }

        if (valid) {
            // ---- O += P @ V (truncated split of P; 3 mma) ----
            #pragma unroll
            for (int ktj = 0; ktj < 8; ktj++) {
                const float* pe = s_fr[2 * ktj];
                const float* po = s_fr[2 * ktj + 1];
                unsigned pah[4], pal[4];
                pah[0] = __byte_perm(__float_as_uint(pe[0]), __float_as_uint(pe[1]), 0x7632);
                pah[1] = __byte_perm(__float_as_uint(pe[2]), __float_as_uint(pe[3]), 0x7632);
                pah[2] = __byte_perm(__float_as_uint(po[0]), __float_as_uint(po[1]), 0x7632);
                pah[3] = __byte_perm(__float_as_uint(po[2]), __float_as_uint(po[3]), 0x7632);
                pal[0] = pack2bf(trunc_resid(pe[0]), trunc_resid(pe[1]));
                pal[1] = pack2bf(trunc_resid(pe[2]), trunc_resid(pe[3]));
                pal[2] = pack2bf(trunc_resid(po[0]), trunc_resid(po[1]));
                pal[3] = pack2bf(trunc_resid(po[2]), trunc_resid(po[3]));

                #pragma unroll
                for (int g = 0; g < 4; g++) {
                    unsigned vbf[4], vlf[4];
                    const int off = (ktj * 16 + (lane & 15)) * KST
                                  + g * 16 + ((lane >> 4) << 3);
                    ldm_x4t(smaddr(&Vh[off]), vbf[0], vbf[1], vbf[2], vbf[3]);
                    ldm_x4t(smaddr(&Vl[off]), vlf[0], vlf[1], vlf[2], vlf[3]);
                    #pragma unroll
                    for (int h2 = 0; h2 < 2; h2++) {
                        const int nd = g * 2 + h2;
                        mma_bf16(o_fr[nd], pah, vbf[h2 * 2], vbf[h2 * 2 + 1]);
                        mma_bf16(o_fr[nd], pal, vbf[h2 * 2], vbf[h2 * 2 + 1]);
                        mma_bf16(o_fr[nd], pah, vlf[h2 * 2], vlf[h2 * 2 + 1]);
                    }
                }
            }
        }
    }

    // ---- epilogue: normalize + store fp32 ----
    const float inv0 = 1.0f / l0;
    const float inv1 = 1.0f / l1;
    const int tr0 = c * WW + half * 128 + w * 16 + (lane >> 2);
    #pragma unroll
    for (int nd = 0; nd < 8; nd++) {
        const int d0 = nd * 8 + (lane & 3) * 2;
        *(float2*)&out[((size_t)b * TT + tr0) * EE + h * SS + d0] =
            make_float2(o_fr[nd][0] * inv0, o_fr[nd][1] * inv0);
        *(float2*)&out[((size_t)b * TT + tr0 + 8) * EE + h * SS + d0] =
            make_float2(o_fr[nd][2] * inv1, o_fr[nd][3] * inv1);
    }
}

// ---------------------------------------------------------------------------
extern "C" void kernel_launch(void* const* d_in, const int* in_sizes, int n_in,
                              void* d_out, int out_size)
{
    const float* x  = (const float*)d_in[0];
    const float* wq = (const float*)d_in[1];
    const float* wk = (const float*)d_in[2];
    const float* wv = (const float*)d_in[3];
    float* out = (float*)d_out;

    cudaFuncSetAttribute(attn_mma_kernel,
                         cudaFuncAttributeMaxDynamicSharedMemorySize, ATT_SMEM_BYTES);

    convert_kernel<<<(NTOT4 + 255) / 256, 256>>>(x, wq, wk, wv);
    qkv_mma_kernel<<<dim3(NN / 128, EE / 128, 3), 256>>>();
    attn_mma_kernel<<<dim3(2 * CC, BB * HH), 256, ATT_SMEM_BYTES>>>(out);
}